// round 1
// baseline (speedup 1.0000x reference)
#include <cuda_runtime.h>
#include <cuda_bf16.h>
#include <math_constants.h>

// Problem constants (shapes fixed by the dataset)
#define NN 50000
#define EE 1600000
#define FDIM 128
#define DENC 32
#define DEMB 12
#define DOUT 44   // DENC + DEMB fused outputs
#define DH 128

// -------- device scratch (static: no allocation allowed) --------
__device__ float g_s[NN];          // s[i] = relu(enc[i]) . w_inf[0:32]
__device__ float g_inf[NN];        // influence logits (base written by encode, edges atomically added)
__device__ float g_emb[NN * DEMB]; // emb[i] = nodes[i] @ W_emb + b_emb
__device__ float g_pmax[128];      // partial maxes
__device__ float g_maxval;         // global max of influence
__device__ float g_accum[13];      // [0:12] = sum w*emb, [12] = sum w

// -------- packed f32x2 helpers --------
__device__ __forceinline__ unsigned long long pack2(float lo, float hi) {
    unsigned long long r;
    asm("mov.b64 %0, {%1, %2};" : "=l"(r) : "r"(__float_as_uint(lo)), "r"(__float_as_uint(hi)));
    return r;
}
__device__ __forceinline__ unsigned long long ffma2(unsigned long long a, unsigned long long b,
                                                    unsigned long long c) {
    unsigned long long d;
    asm("fma.rn.f32x2 %0, %1, %2, %3;" : "=l"(d) : "l"(a), "l"(b), "l"(c));
    return d;
}
__device__ __forceinline__ float lo32(unsigned long long v) { return __uint_as_float((unsigned)(v & 0xFFFFFFFFull)); }
__device__ __forceinline__ float hi32(unsigned long long v) { return __uint_as_float((unsigned)(v >> 32)); }

// ============================================================================
// Kernel A: fused encode. Per thread: 2 nodes, 44 packed accumulators.
//   enc = relu(x @ W_enc + b_enc); s = enc . w_inf; inf0 = s + x[127]*w_inf[32] + b_inf
//   emb = x @ W_emb + b_emb
// ============================================================================
__global__ __launch_bounds__(64) void encode_kernel(
    const float* __restrict__ nodes,
    const float* __restrict__ W_enc, const float* __restrict__ b_enc,
    const float* __restrict__ W_inf, const float* __restrict__ b_inf,
    const float* __restrict__ W_emb, const float* __restrict__ b_emb,
    int n)
{
    __shared__ unsigned long long Wp[FDIM * DOUT];  // weights duplicated into both f32x2 halves
    __shared__ float sh_winf[33];
    __shared__ float sh_b[DOUT];
    __shared__ float sh_binf;

    const int tid = threadIdx.x;
    for (int idx = tid; idx < FDIM * DOUT; idx += blockDim.x) {
        int k = idx / DOUT, j = idx % DOUT;
        float w = (j < DENC) ? W_enc[k * DENC + j] : W_emb[k * DEMB + (j - DENC)];
        unsigned int u = __float_as_uint(w);
        Wp[idx] = ((unsigned long long)u << 32) | u;
    }
    if (tid < 33) sh_winf[tid] = W_inf[tid];
    if (tid < DENC) sh_b[tid] = b_enc[tid];
    if (tid >= DENC && tid < DOUT) sh_b[tid] = b_emb[tid - DENC];
    if (tid == 0) sh_binf = b_inf[0];
    __syncthreads();

    const int base = blockIdx.x * (2 * blockDim.x);
    const int i0 = base + tid;
    const int i1 = base + blockDim.x + tid;
    const bool v0 = (i0 < n), v1 = (i1 < n);
    const float4* r0 = (const float4*)(nodes + (v0 ? (long)i0 * FDIM : 0));
    const float4* r1 = (const float4*)(nodes + (v1 ? (long)i1 * FDIM : 0));

    unsigned long long acc[DOUT];
#pragma unroll
    for (int j = 0; j < DOUT; j++) acc[j] = 0ull;

    float4 a = r0[0], b4 = r1[0];
    float last0 = 0.f, last1 = 0.f;
#pragma unroll 1
    for (int c = 0; c < FDIM / 4; c++) {
        float4 an, bn;
        if (c < FDIM / 4 - 1) { an = r0[c + 1]; bn = r1[c + 1]; }
        unsigned long long x0 = pack2(a.x, b4.x);
        unsigned long long x1 = pack2(a.y, b4.y);
        unsigned long long x2 = pack2(a.z, b4.z);
        unsigned long long x3 = pack2(a.w, b4.w);
        const unsigned long long* w0 = &Wp[(4 * c + 0) * DOUT];
        const unsigned long long* w1 = &Wp[(4 * c + 1) * DOUT];
        const unsigned long long* w2 = &Wp[(4 * c + 2) * DOUT];
        const unsigned long long* w3 = &Wp[(4 * c + 3) * DOUT];
#pragma unroll
        for (int j = 0; j < DOUT; j++) {
            unsigned long long t = acc[j];
            t = ffma2(x0, w0[j], t);
            t = ffma2(x1, w1[j], t);
            t = ffma2(x2, w2[j], t);
            t = ffma2(x3, w3[j], t);
            acc[j] = t;
        }
        if (c == FDIM / 4 - 1) { last0 = a.w; last1 = b4.w; }
        a = an; b4 = bn;
    }

    // epilogue: relu enc, dot with w_inf; emb raw
    float s0 = 0.f, s1 = 0.f;
    float e0j[DENC], e1j[DENC];
#pragma unroll
    for (int j = 0; j < DENC; j++) {
        e0j[j] = fmaxf(lo32(acc[j]) + sh_b[j], 0.f);
        e1j[j] = fmaxf(hi32(acc[j]) + sh_b[j], 0.f);
        s0 += e0j[j] * sh_winf[j];
        s1 += e1j[j] * sh_winf[j];
    }
    if (v0) {
        g_s[i0] = s0;
        g_inf[i0] = s0 + last0 * sh_winf[32] + sh_binf;
        float4* ep = (float4*)(g_emb + (long)i0 * DEMB);
        float4 u;
        u.x = lo32(acc[32]) + sh_b[32]; u.y = lo32(acc[33]) + sh_b[33];
        u.z = lo32(acc[34]) + sh_b[34]; u.w = lo32(acc[35]) + sh_b[35]; ep[0] = u;
        u.x = lo32(acc[36]) + sh_b[36]; u.y = lo32(acc[37]) + sh_b[37];
        u.z = lo32(acc[38]) + sh_b[38]; u.w = lo32(acc[39]) + sh_b[39]; ep[1] = u;
        u.x = lo32(acc[40]) + sh_b[40]; u.y = lo32(acc[41]) + sh_b[41];
        u.z = lo32(acc[42]) + sh_b[42]; u.w = lo32(acc[43]) + sh_b[43]; ep[2] = u;
    }
    if (v1) {
        g_s[i1] = s1;
        g_inf[i1] = s1 + last1 * sh_winf[32] + sh_binf;
        float4* ep = (float4*)(g_emb + (long)i1 * DEMB);
        float4 u;
        u.x = hi32(acc[32]) + sh_b[32]; u.y = hi32(acc[33]) + sh_b[33];
        u.z = hi32(acc[34]) + sh_b[34]; u.w = hi32(acc[35]) + sh_b[35]; ep[0] = u;
        u.x = hi32(acc[36]) + sh_b[36]; u.y = hi32(acc[37]) + sh_b[37];
        u.z = hi32(acc[38]) + sh_b[38]; u.w = hi32(acc[39]) + sh_b[39]; ep[1] = u;
        u.x = hi32(acc[40]) + sh_b[40]; u.y = hi32(acc[41]) + sh_b[41];
        u.z = hi32(acc[42]) + sh_b[42]; u.w = hi32(acc[43]) + sh_b[43]; ep[2] = u;
    }
}

// ============================================================================
// Kernel B: scalar edge scatter: inf[recv] += s[snd]
// ============================================================================
__global__ void scatter_kernel(const int* __restrict__ snd, const int* __restrict__ rcv, int e)
{
    int t = blockIdx.x * blockDim.x + threadIdx.x;
    int base = t * 4;
    if (base + 3 < e) {
        int4 aa = *(const int4*)(snd + base);
        int4 bb = *(const int4*)(rcv + base);
        atomicAdd(&g_inf[bb.x], g_s[aa.x]);
        atomicAdd(&g_inf[bb.y], g_s[aa.y]);
        atomicAdd(&g_inf[bb.z], g_s[aa.z]);
        atomicAdd(&g_inf[bb.w], g_s[aa.w]);
    } else {
        for (int i = base; i < e; i++) atomicAdd(&g_inf[rcv[i]], g_s[snd[i]]);
    }
}

// ============================================================================
// Kernel C1: partial max of influence
// ============================================================================
__global__ void max_kernel(int n)
{
    int stride = gridDim.x * blockDim.x;
    float m = -CUDART_INF_F;
    for (int i = blockIdx.x * blockDim.x + threadIdx.x; i < n; i += stride)
        m = fmaxf(m, g_inf[i]);
#pragma unroll
    for (int o = 16; o; o >>= 1) m = fmaxf(m, __shfl_xor_sync(0xFFFFFFFFu, m, o));
    __shared__ float wm[8];
    if ((threadIdx.x & 31) == 0) wm[threadIdx.x >> 5] = m;
    __syncthreads();
    if (threadIdx.x == 0) {
        float mm = wm[0];
        for (int w = 1; w < (int)(blockDim.x >> 5); w++) mm = fmaxf(mm, wm[w]);
        g_pmax[blockIdx.x] = mm;
    }
}

// Kernel C2: finish max, zero accumulators
__global__ void finalize_max_kernel(int nb)
{
    int t = threadIdx.x;
    float m = (t < nb) ? g_pmax[t] : -CUDART_INF_F;
#pragma unroll
    for (int o = 16; o; o >>= 1) m = fmaxf(m, __shfl_xor_sync(0xFFFFFFFFu, m, o));
    __shared__ float wm[4];
    if ((t & 31) == 0) wm[t >> 5] = m;
    __syncthreads();
    if (t == 0) {
        float mm = fmaxf(fmaxf(wm[0], wm[1]), fmaxf(wm[2], wm[3]));
        g_maxval = mm;
    }
    if (t < 13) g_accum[t] = 0.f;
}

// ============================================================================
// Kernel D: softmax-weighted pooling: accum[j] = sum_i e^{inf_i - max} * emb[i][j], accum[12] = sum e^
// ============================================================================
__global__ void pool_kernel(int n)
{
    const float gm = g_maxval;
    int stride = gridDim.x * blockDim.x;
    float sw = 0.f;
    float gc[DEMB];
#pragma unroll
    for (int j = 0; j < DEMB; j++) gc[j] = 0.f;

    for (int i = blockIdx.x * blockDim.x + threadIdx.x; i < n; i += stride) {
        float w = __expf(g_inf[i] - gm);
        sw += w;
        const float4* ep = (const float4*)(g_emb + (long)i * DEMB);
        float4 e0 = ep[0], e1 = ep[1], e2 = ep[2];
        gc[0] += w * e0.x; gc[1] += w * e0.y; gc[2]  += w * e0.z; gc[3]  += w * e0.w;
        gc[4] += w * e1.x; gc[5] += w * e1.y; gc[6]  += w * e1.z; gc[7]  += w * e1.w;
        gc[8] += w * e2.x; gc[9] += w * e2.y; gc[10] += w * e2.z; gc[11] += w * e2.w;
    }
#pragma unroll
    for (int o = 16; o; o >>= 1) {
        sw += __shfl_xor_sync(0xFFFFFFFFu, sw, o);
#pragma unroll
        for (int j = 0; j < DEMB; j++) gc[j] += __shfl_xor_sync(0xFFFFFFFFu, gc[j], o);
    }
    if ((threadIdx.x & 31) == 0) {
        atomicAdd(&g_accum[12], sw);
#pragma unroll
        for (int j = 0; j < DEMB; j++) atomicAdd(&g_accum[j], gc[j]);
    }
}

// ============================================================================
// Kernel E: head MLP (single block, 128 threads)
// ============================================================================
__global__ __launch_bounds__(DH) void head_kernel(
    const float* __restrict__ W1, const float* __restrict__ b1,
    const float* __restrict__ W2, const float* __restrict__ b2,
    const float* __restrict__ Wy, const float* __restrict__ by,
    const float* __restrict__ Wx, const float* __restrict__ bx,
    float* __restrict__ out)
{
    __shared__ float g[DEMB];
    __shared__ float h1[DH];
    __shared__ float h2[DH];
    const int t = threadIdx.x;
    const float sw = g_accum[12];
    if (t < DEMB) g[t] = g_accum[t] / sw;
    __syncthreads();

    float a = b1[t];
#pragma unroll
    for (int j = 0; j < DEMB; j++) a += g[j] * W1[j * DH + t];
    h1[t] = fmaxf(a, 0.f);
    __syncthreads();

    float c = b2[t];
#pragma unroll 8
    for (int k = 0; k < DH; k++) c += h1[k] * W2[k * DH + t];
    h2[t] = fmaxf(c, 0.f);
    __syncthreads();

    if (t < 4) {
        float o = bx[t];
        for (int k = 0; k < DH; k++) o += h2[k] * Wx[k * 4 + t];
        out[t] = o / 10.0f;
    }
    if (t == 4) {
        float o = by[0];
        for (int k = 0; k < DH; k++) o += h2[k] * Wy[k];
        out[4] = o;
    }
}

// ============================================================================
extern "C" void kernel_launch(void* const* d_in, const int* in_sizes, int n_in,
                              void* d_out, int out_size)
{
    const float* nodes  = (const float*)d_in[0];
    const int*   snd    = (const int*)d_in[1];
    const int*   rcv    = (const int*)d_in[2];
    const float* W_enc  = (const float*)d_in[3];
    const float* b_enc  = (const float*)d_in[4];
    const float* W_inf  = (const float*)d_in[5];
    const float* b_inf  = (const float*)d_in[6];
    const float* W_emb  = (const float*)d_in[7];
    const float* b_emb  = (const float*)d_in[8];
    const float* W1     = (const float*)d_in[9];
    const float* b1     = (const float*)d_in[10];
    const float* W2     = (const float*)d_in[11];
    const float* b2     = (const float*)d_in[12];
    const float* Wy     = (const float*)d_in[13];
    const float* by     = (const float*)d_in[14];
    const float* Wx     = (const float*)d_in[15];
    const float* bx     = (const float*)d_in[16];
    float* out = (float*)d_out;

    const int n = in_sizes[0] / FDIM;   // 50000
    const int e = in_sizes[1];          // 1600000

    // A: encode (2 nodes / thread, 64-thread blocks -> 128 nodes / block)
    int blocksA = (n + 127) / 128;
    encode_kernel<<<blocksA, 64>>>(nodes, W_enc, b_enc, W_inf, b_inf, W_emb, b_emb, n);

    // B: edge scatter (4 edges / thread)
    int threadsB = (e + 3) / 4;
    int blocksB = (threadsB + 255) / 256;
    scatter_kernel<<<blocksB, 256>>>(snd, rcv, e);

    // C: max reduce
    const int NB1 = 120;
    max_kernel<<<NB1, 256>>>(n);
    finalize_max_kernel<<<1, 128>>>(NB1);

    // D: softmax pooling
    pool_kernel<<<232, 256>>>(n);

    // E: head
    head_kernel<<<1, DH>>>(W1, b1, W2, b2, Wy, by, Wx, bx, out);
}

// round 2
// speedup vs baseline: 1.0044x; 1.0044x over previous
#include <cuda_runtime.h>
#include <cuda_bf16.h>
#include <math_constants.h>

// Problem constants (shapes fixed by the dataset)
#define NN 50000
#define EE 1600000
#define FDIM 128
#define DENC 32
#define DEMB 12
#define DOUT 44   // DENC + DEMB fused outputs
#define DH 128

// -------- device scratch (static: no allocation allowed) --------
__device__ float g_s[NN];          // s[i] = relu(enc[i]) . w_inf[0:32]
__device__ float g_inf[NN];        // influence logits (base written by encode, edges atomically added)
__device__ float g_emb[NN * DEMB]; // emb[i] = nodes[i] @ W_emb + b_emb
__device__ float g_pmax[128];      // partial maxes
__device__ float g_maxval;         // global max of influence
__device__ float g_accum[13];      // [0:12] = sum w*emb, [12] = sum w

// -------- packed f32x2 helpers --------
__device__ __forceinline__ unsigned long long pack2(float lo, float hi) {
    unsigned long long r;
    asm("mov.b64 %0, {%1, %2};" : "=l"(r) : "r"(__float_as_uint(lo)), "r"(__float_as_uint(hi)));
    return r;
}
__device__ __forceinline__ unsigned long long ffma2(unsigned long long a, unsigned long long b,
                                                    unsigned long long c) {
    unsigned long long d;
    asm("fma.rn.f32x2 %0, %1, %2, %3;" : "=l"(d) : "l"(a), "l"(b), "l"(c));
    return d;
}
__device__ __forceinline__ float lo32(unsigned long long v) { return __uint_as_float((unsigned)(v & 0xFFFFFFFFull)); }
__device__ __forceinline__ float hi32(unsigned long long v) { return __uint_as_float((unsigned)(v >> 32)); }

// ============================================================================
// Kernel A: fused encode. Per thread: 2 nodes, 44 packed accumulators.
//   enc = relu(x @ W_enc + b_enc); s = enc . w_inf; inf0 = s + x[127]*w_inf[32] + b_inf
//   emb = x @ W_emb + b_emb
// ============================================================================
__global__ __launch_bounds__(64) void encode_kernel(
    const float* __restrict__ nodes,
    const float* __restrict__ W_enc, const float* __restrict__ b_enc,
    const float* __restrict__ W_inf, const float* __restrict__ b_inf,
    const float* __restrict__ W_emb, const float* __restrict__ b_emb,
    int n)
{
    __shared__ unsigned long long Wp[FDIM * DOUT];  // weights duplicated into both f32x2 halves
    __shared__ float sh_winf[33];
    __shared__ float sh_b[DOUT];
    __shared__ float sh_binf;

    const int tid = threadIdx.x;
    for (int idx = tid; idx < FDIM * DOUT; idx += blockDim.x) {
        int k = idx / DOUT, j = idx % DOUT;
        float w = (j < DENC) ? W_enc[k * DENC + j] : W_emb[k * DEMB + (j - DENC)];
        unsigned int u = __float_as_uint(w);
        Wp[idx] = ((unsigned long long)u << 32) | u;
    }
    if (tid < 33) sh_winf[tid] = W_inf[tid];
    if (tid < DENC) sh_b[tid] = b_enc[tid];
    if (tid >= DENC && tid < DOUT) sh_b[tid] = b_emb[tid - DENC];
    if (tid == 0) sh_binf = b_inf[0];
    __syncthreads();

    const int base = blockIdx.x * (2 * blockDim.x);
    const int i0 = base + tid;
    const int i1 = base + blockDim.x + tid;
    const bool v0 = (i0 < n), v1 = (i1 < n);
    const float4* r0 = (const float4*)(nodes + (v0 ? (long)i0 * FDIM : 0));
    const float4* r1 = (const float4*)(nodes + (v1 ? (long)i1 * FDIM : 0));

    unsigned long long acc[DOUT];
#pragma unroll
    for (int j = 0; j < DOUT; j++) acc[j] = 0ull;

    float4 a = r0[0], b4 = r1[0];
    float last0 = 0.f, last1 = 0.f;
#pragma unroll 1
    for (int c = 0; c < FDIM / 4; c++) {
        float4 an, bn;
        if (c < FDIM / 4 - 1) { an = r0[c + 1]; bn = r1[c + 1]; }
        unsigned long long x0 = pack2(a.x, b4.x);
        unsigned long long x1 = pack2(a.y, b4.y);
        unsigned long long x2 = pack2(a.z, b4.z);
        unsigned long long x3 = pack2(a.w, b4.w);
        const unsigned long long* w0 = &Wp[(4 * c + 0) * DOUT];
        const unsigned long long* w1 = &Wp[(4 * c + 1) * DOUT];
        const unsigned long long* w2 = &Wp[(4 * c + 2) * DOUT];
        const unsigned long long* w3 = &Wp[(4 * c + 3) * DOUT];
#pragma unroll
        for (int j = 0; j < DOUT; j++) {
            unsigned long long t = acc[j];
            t = ffma2(x0, w0[j], t);
            t = ffma2(x1, w1[j], t);
            t = ffma2(x2, w2[j], t);
            t = ffma2(x3, w3[j], t);
            acc[j] = t;
        }
        if (c == FDIM / 4 - 1) { last0 = a.w; last1 = b4.w; }
        a = an; b4 = bn;
    }

    // epilogue: relu enc, dot with w_inf; emb raw
    float s0 = 0.f, s1 = 0.f;
    float e0j[DENC], e1j[DENC];
#pragma unroll
    for (int j = 0; j < DENC; j++) {
        e0j[j] = fmaxf(lo32(acc[j]) + sh_b[j], 0.f);
        e1j[j] = fmaxf(hi32(acc[j]) + sh_b[j], 0.f);
        s0 += e0j[j] * sh_winf[j];
        s1 += e1j[j] * sh_winf[j];
    }
    if (v0) {
        g_s[i0] = s0;
        g_inf[i0] = s0 + last0 * sh_winf[32] + sh_binf;
        float4* ep = (float4*)(g_emb + (long)i0 * DEMB);
        float4 u;
        u.x = lo32(acc[32]) + sh_b[32]; u.y = lo32(acc[33]) + sh_b[33];
        u.z = lo32(acc[34]) + sh_b[34]; u.w = lo32(acc[35]) + sh_b[35]; ep[0] = u;
        u.x = lo32(acc[36]) + sh_b[36]; u.y = lo32(acc[37]) + sh_b[37];
        u.z = lo32(acc[38]) + sh_b[38]; u.w = lo32(acc[39]) + sh_b[39]; ep[1] = u;
        u.x = lo32(acc[40]) + sh_b[40]; u.y = lo32(acc[41]) + sh_b[41];
        u.z = lo32(acc[42]) + sh_b[42]; u.w = lo32(acc[43]) + sh_b[43]; ep[2] = u;
    }
    if (v1) {
        g_s[i1] = s1;
        g_inf[i1] = s1 + last1 * sh_winf[32] + sh_binf;
        float4* ep = (float4*)(g_emb + (long)i1 * DEMB);
        float4 u;
        u.x = hi32(acc[32]) + sh_b[32]; u.y = hi32(acc[33]) + sh_b[33];
        u.z = hi32(acc[34]) + sh_b[34]; u.w = hi32(acc[35]) + sh_b[35]; ep[0] = u;
        u.x = hi32(acc[36]) + sh_b[36]; u.y = hi32(acc[37]) + sh_b[37];
        u.z = hi32(acc[38]) + sh_b[38]; u.w = hi32(acc[39]) + sh_b[39]; ep[1] = u;
        u.x = hi32(acc[40]) + sh_b[40]; u.y = hi32(acc[41]) + sh_b[41];
        u.z = hi32(acc[42]) + sh_b[42]; u.w = hi32(acc[43]) + sh_b[43]; ep[2] = u;
    }
}

// ============================================================================
// Kernel B: scalar edge scatter: inf[recv] += s[snd]
// ============================================================================
__global__ void scatter_kernel(const int* __restrict__ snd, const int* __restrict__ rcv, int e)
{
    int t = blockIdx.x * blockDim.x + threadIdx.x;
    int base = t * 4;
    if (base + 3 < e) {
        int4 aa = *(const int4*)(snd + base);
        int4 bb = *(const int4*)(rcv + base);
        atomicAdd(&g_inf[bb.x], g_s[aa.x]);
        atomicAdd(&g_inf[bb.y], g_s[aa.y]);
        atomicAdd(&g_inf[bb.z], g_s[aa.z]);
        atomicAdd(&g_inf[bb.w], g_s[aa.w]);
    } else {
        for (int i = base; i < e; i++) atomicAdd(&g_inf[rcv[i]], g_s[snd[i]]);
    }
}

// ============================================================================
// Kernel C1: partial max of influence
// ============================================================================
__global__ void max_kernel(int n)
{
    int stride = gridDim.x * blockDim.x;
    float m = -CUDART_INF_F;
    for (int i = blockIdx.x * blockDim.x + threadIdx.x; i < n; i += stride)
        m = fmaxf(m, g_inf[i]);
#pragma unroll
    for (int o = 16; o; o >>= 1) m = fmaxf(m, __shfl_xor_sync(0xFFFFFFFFu, m, o));
    __shared__ float wm[8];
    if ((threadIdx.x & 31) == 0) wm[threadIdx.x >> 5] = m;
    __syncthreads();
    if (threadIdx.x == 0) {
        float mm = wm[0];
        for (int w = 1; w < (int)(blockDim.x >> 5); w++) mm = fmaxf(mm, wm[w]);
        g_pmax[blockIdx.x] = mm;
    }
}

// Kernel C2: finish max, zero accumulators
__global__ void finalize_max_kernel(int nb)
{
    int t = threadIdx.x;
    float m = (t < nb) ? g_pmax[t] : -CUDART_INF_F;
#pragma unroll
    for (int o = 16; o; o >>= 1) m = fmaxf(m, __shfl_xor_sync(0xFFFFFFFFu, m, o));
    __shared__ float wm[4];
    if ((t & 31) == 0) wm[t >> 5] = m;
    __syncthreads();
    if (t == 0) {
        float mm = fmaxf(fmaxf(wm[0], wm[1]), fmaxf(wm[2], wm[3]));
        g_maxval = mm;
    }
    if (t < 13) g_accum[t] = 0.f;
}

// ============================================================================
// Kernel D: softmax-weighted pooling: accum[j] = sum_i e^{inf_i - max} * emb[i][j], accum[12] = sum e^
// ============================================================================
__global__ void pool_kernel(int n)
{
    const float gm = g_maxval;
    int stride = gridDim.x * blockDim.x;
    float sw = 0.f;
    float gc[DEMB];
#pragma unroll
    for (int j = 0; j < DEMB; j++) gc[j] = 0.f;

    for (int i = blockIdx.x * blockDim.x + threadIdx.x; i < n; i += stride) {
        float w = __expf(g_inf[i] - gm);
        sw += w;
        const float4* ep = (const float4*)(g_emb + (long)i * DEMB);
        float4 e0 = ep[0], e1 = ep[1], e2 = ep[2];
        gc[0] += w * e0.x; gc[1] += w * e0.y; gc[2]  += w * e0.z; gc[3]  += w * e0.w;
        gc[4] += w * e1.x; gc[5] += w * e1.y; gc[6]  += w * e1.z; gc[7]  += w * e1.w;
        gc[8] += w * e2.x; gc[9] += w * e2.y; gc[10] += w * e2.z; gc[11] += w * e2.w;
    }
#pragma unroll
    for (int o = 16; o; o >>= 1) {
        sw += __shfl_xor_sync(0xFFFFFFFFu, sw, o);
#pragma unroll
        for (int j = 0; j < DEMB; j++) gc[j] += __shfl_xor_sync(0xFFFFFFFFu, gc[j], o);
    }
    if ((threadIdx.x & 31) == 0) {
        atomicAdd(&g_accum[12], sw);
#pragma unroll
        for (int j = 0; j < DEMB; j++) atomicAdd(&g_accum[j], gc[j]);
    }
}

// ============================================================================
// Kernel E: head MLP (single block, 128 threads)
// ============================================================================
__global__ __launch_bounds__(DH) void head_kernel(
    const float* __restrict__ W1, const float* __restrict__ b1,
    const float* __restrict__ W2, const float* __restrict__ b2,
    const float* __restrict__ Wy, const float* __restrict__ by,
    const float* __restrict__ Wx, const float* __restrict__ bx,
    float* __restrict__ out)
{
    __shared__ float g[DEMB];
    __shared__ float h1[DH];
    __shared__ float h2[DH];
    const int t = threadIdx.x;
    const float sw = g_accum[12];
    if (t < DEMB) g[t] = g_accum[t] / sw;
    __syncthreads();

    float a = b1[t];
#pragma unroll
    for (int j = 0; j < DEMB; j++) a += g[j] * W1[j * DH + t];
    h1[t] = fmaxf(a, 0.f);
    __syncthreads();

    float c = b2[t];
#pragma unroll 8
    for (int k = 0; k < DH; k++) c += h1[k] * W2[k * DH + t];
    h2[t] = fmaxf(c, 0.f);
    __syncthreads();

    if (t < 4) {
        float o = bx[t];
        for (int k = 0; k < DH; k++) o += h2[k] * Wx[k * 4 + t];
        out[t] = o / 10.0f;
    }
    if (t == 4) {
        float o = by[0];
        for (int k = 0; k < DH; k++) o += h2[k] * Wy[k];
        out[4] = o;
    }
}

// ============================================================================
extern "C" void kernel_launch(void* const* d_in, const int* in_sizes, int n_in,
                              void* d_out, int out_size)
{
    const float* nodes  = (const float*)d_in[0];
    const int*   snd    = (const int*)d_in[1];
    const int*   rcv    = (const int*)d_in[2];
    const float* W_enc  = (const float*)d_in[3];
    const float* b_enc  = (const float*)d_in[4];
    const float* W_inf  = (const float*)d_in[5];
    const float* b_inf  = (const float*)d_in[6];
    const float* W_emb  = (const float*)d_in[7];
    const float* b_emb  = (const float*)d_in[8];
    const float* W1     = (const float*)d_in[9];
    const float* b1     = (const float*)d_in[10];
    const float* W2     = (const float*)d_in[11];
    const float* b2     = (const float*)d_in[12];
    const float* Wy     = (const float*)d_in[13];
    const float* by     = (const float*)d_in[14];
    const float* Wx     = (const float*)d_in[15];
    const float* bx     = (const float*)d_in[16];
    float* out = (float*)d_out;

    const int n = in_sizes[0] / FDIM;   // 50000
    const int e = in_sizes[1];          // 1600000

    // A: encode (2 nodes / thread, 64-thread blocks -> 128 nodes / block)
    int blocksA = (n + 127) / 128;
    encode_kernel<<<blocksA, 64>>>(nodes, W_enc, b_enc, W_inf, b_inf, W_emb, b_emb, n);

    // B: edge scatter (4 edges / thread)
    int threadsB = (e + 3) / 4;
    int blocksB = (threadsB + 255) / 256;
    scatter_kernel<<<blocksB, 256>>>(snd, rcv, e);

    // C: max reduce
    const int NB1 = 120;
    max_kernel<<<NB1, 256>>>(n);
    finalize_max_kernel<<<1, 128>>>(NB1);

    // D: softmax pooling
    pool_kernel<<<232, 256>>>(n);

    // E: head
    head_kernel<<<1, DH>>>(W1, b1, W2, b2, Wy, by, Wx, bx, out);
}